// round 6
// baseline (speedup 1.0000x reference)
#include <cuda_runtime.h>
#include <cstdint>

#define DEVINL __device__ __forceinline__

constexpr int B = 4, N = 4096, K = 10, BN = B * N;
constexpr float SLOPE = 0.2f;
constexpr float BNS = 0.9999950000374997f; // 1/sqrt(1+1e-5)
constexpr float NEG_INF = -3.4e38f;

DEVINL void fma2(unsigned long long& acc, unsigned long long a, unsigned long long b) {
    asm("fma.rn.f32x2 %0, %1, %2, %0;" : "+l"(acc) : "l"(a), "l"(b));
}
DEVINL unsigned long long fma2v(unsigned long long a, unsigned long long b, unsigned long long c) {
    unsigned long long d;
    asm("fma.rn.f32x2 %0, %1, %2, %3;" : "=l"(d) : "l"(a), "l"(b), "l"(c));
    return d;
}
DEVINL unsigned long long dup2(float v) {
    unsigned long long r;
    asm("mov.b64 %0, {%1, %1};" : "=l"(r) : "f"(v));
    return r;
}
DEVINL float f2sum(unsigned long long v) {
    float2 f = *reinterpret_cast<float2*>(&v);
    return f.x + f.y;
}
DEVINL float2 f2of(unsigned long long v) { return *reinterpret_cast<float2*>(&v); }
struct U64x2 { unsigned long long a, b; };
DEVINL U64x2 asu64x2(const float4& v) {
    U64x2 r;
    r.a = *reinterpret_cast<const unsigned long long*>(&v.x);
    r.b = *reinterpret_cast<const unsigned long long*>(&v.z);
    return r;
}

#define CP16(dst, src) asm volatile("cp.async.cg.shared.global [%0], [%1], 16;" :: "r"(dst), "l"(src))
#define CP_COMMIT() asm volatile("cp.async.commit_group;" ::: "memory")
template<int NN>
DEVINL void cp_wait() { asm volatile("cp.async.wait_group %0;" :: "n"(NN) : "memory"); }

// ---------------- scratch ----------------
__device__ float g_cat[BN * 512];
__device__ float g_catT[512 * BN];
__device__ float g_AC[BN * 512];
__device__ float g_sq[BN];
__device__ int   g_knn[BN * K];
__device__ float g_w5t[512 * 1024];
__device__ float g_part[256 * 1024];
__device__ float g_h0[B * 1024];
__device__ float g_y1[B * 512];
__device__ float g_y2[B * 256];

// ================= layer-1 kNN (D=3), inline ||c||^2 =================
__global__ void __launch_bounds__(256) knn1_kernel(const float* __restrict__ x) {
    constexpr int CR4 = 32;
    extern __shared__ __align__(16) char smem[];
    float4* Q4 = (float4*)smem;                          // 64
    float4* C4 = (float4*)(smem + 64 * 16);              // 2*32
    float*  Ss = (float*)(smem + 64 * 16 + 2 * CR4 * 16);// 64*33
    float*  Mv = (float*)smem;
    int*    Mi = (int*)(smem + 64 * 4 * K * 4);

    int tid = threadIdx.x;
    int tx = tid & 15, ty = tid >> 4;
    int rq = tid & 63, rs = tid >> 6;
    int b = blockIdx.y, qbase = blockIdx.x * 64;
    const float* xb = x + (size_t)b * N * 3;
    int qglob = qbase + rq;

    float lv[K]; int li[K];
#pragma unroll
    for (int j = 0; j < K; ++j) { lv[j] = NEG_INF; li[j] = 0x7fffffff; }

    for (int i = tid; i < 64; i += 256) {
        const float* p = xb + (size_t)(qbase + i) * 3;
        Q4[i] = make_float4(p[0], p[1], p[2], 0.f);
    }

    float4 creg;
    auto load_c = [&](int cb) {
        if (tid < 32) {
            const float* p = xb + (size_t)(cb + tid) * 3;
            creg = make_float4(p[0], p[1], p[2], 0.f);
        }
    };
    load_c(0);

    for (int cb = 0; cb < N; cb += 32) {
        int buf = (cb >> 5) & 1;
        if (tid < 32) C4[buf * CR4 + tid] = creg;
        if (cb + 32 < N) load_c(cb + 32);
        __syncthreads();

        const float4* Cb = C4 + buf * CR4;
        U64x2 qv[4], cv[2];
#pragma unroll
        for (int qi = 0; qi < 4; ++qi) qv[qi] = asu64x2(Q4[ty + 16 * qi]);
#pragma unroll
        for (int ci = 0; ci < 2; ++ci) cv[ci] = asu64x2(Cb[tx + 16 * ci]);

        // inline candidate squared norms
        float sc[2];
#pragma unroll
        for (int ci = 0; ci < 2; ++ci) {
            unsigned long long a = 0ull;
            fma2(a, cv[ci].a, cv[ci].a);
            fma2(a, cv[ci].b, cv[ci].b);
            sc[ci] = f2sum(a);
        }

        unsigned long long acc2[4][2];
#pragma unroll
        for (int qi = 0; qi < 4; ++qi) { acc2[qi][0] = 0ull; acc2[qi][1] = 0ull; }
#pragma unroll
        for (int qi = 0; qi < 4; ++qi)
#pragma unroll
            for (int ci = 0; ci < 2; ++ci) {
                fma2(acc2[qi][ci], qv[qi].a, cv[ci].a);
                fma2(acc2[qi][ci], qv[qi].b, cv[ci].b);
            }
#pragma unroll
        for (int qi = 0; qi < 4; ++qi) {
            Ss[(ty + 16 * qi) * 33 + tx]      = 2.f * f2sum(acc2[qi][0]) - sc[0];
            Ss[(ty + 16 * qi) * 33 + tx + 16] = 2.f * f2sum(acc2[qi][1]) - sc[1];
        }
        __syncthreads();

#pragma unroll
        for (int j = 0; j < 8; ++j) {
            int c = cb + rs * 8 + j;
            float v = Ss[rq * 33 + rs * 8 + j];
            if (c != qglob) {
                if (v > lv[K - 1] || (v == lv[K - 1] && c < li[K - 1])) {
                    float cvv = v; int cid = c;
#pragma unroll
                    for (int t = 0; t < K; ++t) {
                        bool better = (cvv > lv[t]) || (cvv == lv[t] && cid < li[t]);
                        float tv = lv[t]; int ti = li[t];
                        if (better) { lv[t] = cvv; li[t] = cid; cvv = tv; cid = ti; }
                    }
                }
            }
        }
        __syncthreads();
    }
    __syncthreads();

#pragma unroll
    for (int j = 0; j < K; ++j) {
        Mv[(rq * 4 + rs) * K + j] = lv[j];
        Mi[(rq * 4 + rs) * K + j] = li[j];
    }
    __syncthreads();
    if (tid < 64) {
        int h[4] = {0, 0, 0, 0};
        int base = tid * 4 * K;
        int* out = g_knn + (size_t)(b * N + qbase + tid) * K;
        for (int j = 0; j < K; ++j) {
            float bv = NEG_INF; int bi = 0x7fffffff; int bs = 0;
#pragma unroll
            for (int s = 0; s < 4; ++s) {
                if (h[s] < K) {
                    float v = Mv[base + s * K + h[s]];
                    int   i = Mi[base + s * K + h[s]];
                    if (v > bv || (v == bv && i < bi)) { bv = v; bi = i; bs = s; }
                }
            }
            h[bs]++;
            out[j] = bi;
        }
    }
}

// ================= outer-product kNN for D in {64,128} =================
template<int D>
__global__ void __launch_bounds__(256) knn2_kernel(int xtoff) {
    extern __shared__ __align__(16) float sm2[];
    float* Qt  = sm2;
    float* Ct  = Qt + D * 128;
    float* nsq = Ct + D * 128;
    float* Ss  = nsq + 128;
    float* Mv  = sm2;
    int*   Mi  = (int*)(sm2 + 128 * 2 * K);

    int tid = threadIdx.x;
    int tx = tid & 15, ty = tid >> 4;
    int b = blockIdx.y, qbase = blockIdx.x * 128;
    int base = b * 4096;
    const float* xt = g_catT + (size_t)xtoff * BN;
    const float* sqb = g_sq + base;

#pragma unroll 4
    for (int i = tid; i < D * 32; i += 256) {
        int d = i >> 5, n4 = (i & 31) << 2;
        *(float4*)(Qt + d * 128 + n4) = *(const float4*)(xt + (size_t)d * BN + base + qbase + n4);
    }

    int q = tid >> 1, rs = tid & 1;
    int qglob = qbase + q;
    float lv[K]; int li[K];
#pragma unroll
    for (int j = 0; j < K; ++j) { lv[j] = NEG_INF; li[j] = 0x7fffffff; }

    unsigned long long two2 = dup2(2.0f);

    for (int cb = 0; cb < N; cb += 128) {
#pragma unroll 4
        for (int i = tid; i < D * 32; i += 256) {
            int d = i >> 5, n4 = (i & 31) << 2;
            *(float4*)(Ct + d * 128 + n4) = *(const float4*)(xt + (size_t)d * BN + base + cb + n4);
        }
        if (tid < 128) nsq[tid] = -sqb[cb + tid];
        __syncthreads();

        unsigned long long acc[8][4];
#pragma unroll
        for (int qi = 0; qi < 8; ++qi)
#pragma unroll
            for (int j = 0; j < 4; ++j) acc[qi][j] = 0ull;

#pragma unroll 4
        for (int d = 0; d < D; ++d) {
            const float* Qr = Qt + d * 128 + ty * 8;
            const float* Cr = Ct + d * 128 + tx * 8;
            float4 qa = *(const float4*)Qr;
            float4 qb = *(const float4*)(Qr + 4);
            U64x2 c01 = asu64x2(*(const float4*)Cr);
            U64x2 c23 = asu64x2(*(const float4*)(Cr + 4));
            unsigned long long qq[8];
            qq[0] = dup2(qa.x); qq[1] = dup2(qa.y); qq[2] = dup2(qa.z); qq[3] = dup2(qa.w);
            qq[4] = dup2(qb.x); qq[5] = dup2(qb.y); qq[6] = dup2(qb.z); qq[7] = dup2(qb.w);
#pragma unroll
            for (int qi = 0; qi < 8; ++qi) {
                fma2(acc[qi][0], qq[qi], c01.a);
                fma2(acc[qi][1], qq[qi], c01.b);
                fma2(acc[qi][2], qq[qi], c23.a);
                fma2(acc[qi][3], qq[qi], c23.b);
            }
        }

#pragma unroll
        for (int j = 0; j < 4; ++j) {
            unsigned long long ns = *(const unsigned long long*)(nsq + tx * 8 + 2 * j);
#pragma unroll
            for (int qi = 0; qi < 8; ++qi) {
                unsigned long long s = fma2v(acc[qi][j], two2, ns);
                *(unsigned long long*)(Ss + (size_t)(ty * 8 + qi) * 132 + tx * 8 + 2 * j) = s;
            }
        }
        __syncthreads();

        const float* Sr = Ss + (size_t)q * 132 + rs * 64;
#pragma unroll 4
        for (int j = 0; j < 64; ++j) {
            int c = cb + rs * 64 + j;
            float v = Sr[j];
            if (c != qglob) {
                if (v > lv[K - 1] || (v == lv[K - 1] && c < li[K - 1])) {
                    float cvv = v; int cid = c;
#pragma unroll
                    for (int t = 0; t < K; ++t) {
                        bool better = (cvv > lv[t]) || (cvv == lv[t] && cid < li[t]);
                        float tv = lv[t]; int ti = li[t];
                        if (better) { lv[t] = cvv; li[t] = cid; cvv = tv; cid = ti; }
                    }
                }
            }
        }
        __syncthreads();
    }

#pragma unroll
    for (int j = 0; j < K; ++j) {
        Mv[(q * 2 + rs) * K + j] = lv[j];
        Mi[(q * 2 + rs) * K + j] = li[j];
    }
    __syncthreads();
    if (tid < 128) {
        int h0 = 0, h1 = 0;
        int base2 = tid * 2 * K;
        int* out = g_knn + (size_t)(b * N + qbase + tid) * K;
        for (int j = 0; j < K; ++j) {
            float v0 = (h0 < K) ? Mv[base2 + h0] : NEG_INF;
            int   i0 = (h0 < K) ? Mi[base2 + h0] : 0x7fffffff;
            float v1 = (h1 < K) ? Mv[base2 + K + h1] : NEG_INF;
            int   i1 = (h1 < K) ? Mi[base2 + K + h1] : 0x7fffffff;
            bool take0 = (v0 > v1) || (v0 == v1 && i0 < i1);
            out[j] = take0 ? i0 : i1;
            if (take0) h0++; else h1++;
        }
    }
}

// ---------------- AC GEMM with inline weight prep ----------------
// out = X @ wc^T, wc = [w[:, :D] ; w[:, D:] - w[:, :D]], raw w is O x 2D.
template<int DPAD>
__global__ void __launch_bounds__(256) gemm_kernel(
    const float* __restrict__ xext, int xoff, int ldx,
    const float* __restrict__ wraw, int D, int O, int ldo)
{
    constexpr int DC  = (DPAD < 32) ? DPAD : 32;
    constexpr int RC  = DC / 4;
    constexpr int SWM = (RC >= 8) ? 7 : 0;
    constexpr int NCH = DPAD / DC;
    constexpr int TR4 = 64 * RC;
    constexpr int NL  = (TR4 + 255) / 256;
    __shared__ float4 Xs[2 * TR4];
    __shared__ float4 Ws[2 * TR4];
    const float* x = xext ? xext : (g_cat + xoff);
    int tid = threadIdx.x, tx = tid & 15, ty = tid >> 4;
    int rowbase = blockIdx.x * 64, colbase = blockIdx.y * 64;
    unsigned long long acc2[4][4];
#pragma unroll
    for (int qi = 0; qi < 4; ++qi)
#pragma unroll
        for (int ci = 0; ci < 4; ++ci) acc2[qi][ci] = 0ull;

    float4 xreg[NL], wreg[NL];
    auto load_xw = [&](int ch) {
        int d0 = ch * DC;
#pragma unroll
        for (int l = 0; l < NL; ++l) {
            int i = tid + l * 256;
            if ((TR4 % 256 == 0) || i < TR4) {
                int r = i / RC, dv = i % RC;
                int cr = colbase + r;
                if constexpr (DPAD == 4) {
                    const float* p = x + (size_t)(rowbase + r) * ldx;
                    xreg[l] = make_float4(p[0], p[1], p[2], 0.f);
                    float vv[4];
#pragma unroll
                    for (int e = 0; e < 4; ++e) {
                        float v = 0.f;
                        if (e < 3) {
                            if (cr < O) v = wraw[cr * 6 + e];
                            else { int o = cr - O; v = wraw[o * 6 + 3 + e] - wraw[o * 6 + e]; }
                        }
                        vv[e] = v;
                    }
                    wreg[l] = make_float4(vv[0], vv[1], vv[2], vv[3]);
                } else {
                    xreg[l] = *(const float4*)(x + (size_t)(rowbase + r) * ldx + d0 + 4 * dv);
                    if (cr < O) {
                        wreg[l] = *(const float4*)(wraw + (size_t)cr * 2 * D + d0 + 4 * dv);
                    } else {
                        int o = cr - O;
                        float4 a = *(const float4*)(wraw + (size_t)o * 2 * D + D + d0 + 4 * dv);
                        float4 bq = *(const float4*)(wraw + (size_t)o * 2 * D + d0 + 4 * dv);
                        wreg[l] = make_float4(a.x - bq.x, a.y - bq.y, a.z - bq.z, a.w - bq.w);
                    }
                }
            }
        }
    };
    auto store_xw = [&](int buf) {
#pragma unroll
        for (int l = 0; l < NL; ++l) {
            int i = tid + l * 256;
            if ((TR4 % 256 == 0) || i < TR4) {
                int r = i / RC, dv = i % RC;
                Xs[buf * TR4 + r * RC + (dv ^ (r & SWM))] = xreg[l];
                Ws[buf * TR4 + r * RC + (dv ^ (r & SWM))] = wreg[l];
            }
        }
    };

    load_xw(0);
    for (int ch = 0; ch < NCH; ++ch) {
        int buf = ch & 1;
        store_xw(buf);
        if (ch + 1 < NCH) load_xw(ch + 1);
        __syncthreads();
        const float4* Xb = Xs + buf * TR4;
        const float4* Wb = Ws + buf * TR4;
#pragma unroll
        for (int dv = 0; dv < RC; ++dv) {
            U64x2 xv[4], wv[4];
#pragma unroll
            for (int qi = 0; qi < 4; ++qi)
                xv[qi] = asu64x2(Xb[(ty + 16 * qi) * RC + (dv ^ (ty & SWM))]);
#pragma unroll
            for (int ci = 0; ci < 4; ++ci)
                wv[ci] = asu64x2(Wb[(tx + 16 * ci) * RC + (dv ^ (tx & SWM))]);
#pragma unroll
            for (int qi = 0; qi < 4; ++qi)
#pragma unroll
                for (int ci = 0; ci < 4; ++ci) {
                    fma2(acc2[qi][ci], xv[qi].a, wv[ci].a);
                    fma2(acc2[qi][ci], xv[qi].b, wv[ci].b);
                }
        }
        __syncthreads();
    }
#pragma unroll
    for (int qi = 0; qi < 4; ++qi)
#pragma unroll
        for (int ci = 0; ci < 4; ++ci)
            g_AC[(size_t)(rowbase + ty + 16 * qi) * ldo + colbase + tx + 16 * ci] =
                f2sum(acc2[qi][ci]);
}

// ---------------- w5 transpose prep ----------------
__global__ void prep_w5t_kernel(const float* __restrict__ w5) {
    int i = blockIdx.x * blockDim.x + threadIdx.x;
    if (i >= 512 * 1024) return;
    int o = i >> 9, k = i & 511;
    g_w5t[k * 1024 + o] = w5[o * 512 + k];
}

// ================= w5 GEMM: outer-product + cp.async + fused epilogue ======
__global__ void __launch_bounds__(256) gemm5_kernel(const float* __restrict__ gg,
                                                    const float* __restrict__ bb) {
    constexpr int KC = 32, NCH = 512 / KC;
    extern __shared__ __align__(16) float sm5[];
    float* Xs = sm5;
    float* Ws = sm5 + 8192;
    int tid = threadIdx.x;
    int tx = tid & 15, ty = tid >> 4;
    int rowbase = blockIdx.x * 128, colbase = blockIdx.y * 128;

    unsigned long long acc[8][4];
#pragma unroll
    for (int qi = 0; qi < 8; ++qi)
#pragma unroll
        for (int j = 0; j < 4; ++j) acc[qi][j] = 0ull;

    auto issue = [&](int ch, int buf) {
#pragma unroll
        for (int l = 0; l < 4; ++l) {
            int i = tid + l * 256;
            int dk = i >> 5, n4 = (i & 31) << 2;
            unsigned xdst = (unsigned)__cvta_generic_to_shared(Xs + buf * 4096 + dk * 128 + n4);
            unsigned wdst = (unsigned)__cvta_generic_to_shared(Ws + buf * 4096 + dk * 128 + n4);
            CP16(xdst, g_catT + (size_t)(ch * KC + dk) * BN + rowbase + n4);
            CP16(wdst, g_w5t + (size_t)(ch * KC + dk) * 1024 + colbase + n4);
        }
        CP_COMMIT();
    };

    issue(0, 0);
    for (int ch = 0; ch < NCH; ++ch) {
        int buf = ch & 1;
        if (ch + 1 < NCH) { issue(ch + 1, buf ^ 1); cp_wait<1>(); }
        else cp_wait<0>();
        __syncthreads();
#pragma unroll 4
        for (int k = 0; k < KC; ++k) {
            const float* Xr = Xs + buf * 4096 + k * 128 + ty * 8;
            const float* Wr = Ws + buf * 4096 + k * 128 + tx * 8;
            float4 xa = *(const float4*)Xr;
            float4 xb = *(const float4*)(Xr + 4);
            U64x2 w01 = asu64x2(*(const float4*)Wr);
            U64x2 w23 = asu64x2(*(const float4*)(Wr + 4));
            unsigned long long qq[8];
            qq[0] = dup2(xa.x); qq[1] = dup2(xa.y); qq[2] = dup2(xa.z); qq[3] = dup2(xa.w);
            qq[4] = dup2(xb.x); qq[5] = dup2(xb.y); qq[6] = dup2(xb.z); qq[7] = dup2(xb.w);
#pragma unroll
            for (int qi = 0; qi < 8; ++qi) {
                fma2(acc[qi][0], qq[qi], w01.a);
                fma2(acc[qi][1], qq[qi], w01.b);
                fma2(acc[qi][2], qq[qi], w23.a);
                fma2(acc[qi][3], qq[qi], w23.b);
            }
        }
        __syncthreads();
    }

    float* R = Xs;
#pragma unroll
    for (int j = 0; j < 4; ++j) {
        int c0 = colbase + tx * 8 + 2 * j;
        float ga0 = BNS * gg[c0], be0 = bb[c0];
        float ga1 = BNS * gg[c0 + 1], be1 = bb[c0 + 1];
        float m0 = NEG_INF, m1 = NEG_INF;
#pragma unroll
        for (int qi = 0; qi < 8; ++qi) {
            float2 f = f2of(acc[qi][j]);
            float v0 = ga0 * f.x + be0; v0 = (v0 > 0.f) ? v0 : SLOPE * v0;
            float v1 = ga1 * f.y + be1; v1 = (v1 > 0.f) ? v1 : SLOPE * v1;
            m0 = fmaxf(m0, v0); m1 = fmaxf(m1, v1);
        }
        R[ty * 128 + tx * 8 + 2 * j]     = m0;
        R[ty * 128 + tx * 8 + 2 * j + 1] = m1;
    }
    __syncthreads();
    if (tid < 128) {
        float m = R[tid];
#pragma unroll
        for (int t = 1; t < 16; ++t) m = fmaxf(m, R[t * 128 + tid]);
        g_part[(size_t)blockIdx.x * 1024 + colbase + tid] = m;
    }
}

// ---------------- gather + bn + lrelu + max, fused next-layer sqnorm -------
__global__ void edgemax_kernel(const float* __restrict__ gamma, const float* __restrict__ beta,
                               int O, int catoff) {
    int n = blockIdx.x;
    int o = threadIdx.x;
    int b = n >> 12;
    __shared__ int sidx[K];
    __shared__ float ps[8];
    if (o < K) sidx[o] = g_knn[(size_t)n * K + o];
    __syncthreads();
    int twoO = 2 * O;
    float cterm = g_AC[(size_t)n * twoO + O + o];
    float g = BNS * gamma[o], be = beta[o];
    int base = b << 12;
    float m = NEG_INF;
#pragma unroll
    for (int j = 0; j < K; ++j) {
        float a = g_AC[(size_t)(base + sidx[j]) * twoO + o];
        float v = g * (a + cterm) + be;
        v = (v > 0.f) ? v : SLOPE * v;
        m = fmaxf(m, v);
    }
    g_cat[(size_t)n * 512 + catoff + o] = m;
    g_catT[(size_t)(catoff + o) * BN + n] = m;

    // fused squared-norm of this layer's output row (for next layer's kNN)
    float p = m * m;
#pragma unroll
    for (int off = 16; off; off >>= 1) p += __shfl_down_sync(0xffffffffu, p, off);
    if ((o & 31) == 0) ps[o >> 5] = p;
    __syncthreads();
    if (o == 0) {
        float s = 0.f;
        int nw = O >> 5;
        for (int w = 0; w < nw; ++w) s += ps[w];
        g_sq[n] = s;
    }
}

// ---------------- final max reduce + warp-per-output MLP head ----------------
__global__ void maxreduce_kernel() {
    int i = blockIdx.x * blockDim.x + threadIdx.x;
    if (i >= B * 1024) return;
    int b = i / 1024, o = i % 1024;
    float m = NEG_INF;
    for (int j = 0; j < 32; ++j)
        m = fmaxf(m, g_part[(size_t)(b * 32 + j) * 1024 + o]);
    g_h0[i] = m;
}

__global__ void fc1_kernel(const float* __restrict__ fw1, const float* __restrict__ fg1,
                           const float* __restrict__ fbt1) {
    int gw = (blockIdx.x * blockDim.x + threadIdx.x) >> 5;
    int lane = threadIdx.x & 31;
    if (gw >= B * 512) return;
    int b = gw >> 9, o = gw & 511;
    const float* h = g_h0 + b * 1024;
    const float* wr = fw1 + (size_t)o * 1024;
    float s = 0.f;
    for (int c = lane; c < 1024; c += 32) s += h[c] * wr[c];
#pragma unroll
    for (int off = 16; off; off >>= 1) s += __shfl_down_sync(0xffffffffu, s, off);
    if (lane == 0) {
        float v = BNS * fg1[o] * s + fbt1[o];
        g_y1[gw] = (v > 0.f) ? v : SLOPE * v;
    }
}

__global__ void fc2_kernel(const float* __restrict__ fw2, const float* __restrict__ fb2,
                           const float* __restrict__ fg2, const float* __restrict__ fbt2) {
    int gw = (blockIdx.x * blockDim.x + threadIdx.x) >> 5;
    int lane = threadIdx.x & 31;
    if (gw >= B * 256) return;
    int b = gw >> 8, o = gw & 255;
    const float* h = g_y1 + b * 512;
    const float* wr = fw2 + (size_t)o * 512;
    float s = 0.f;
    for (int c = lane; c < 512; c += 32) s += h[c] * wr[c];
#pragma unroll
    for (int off = 16; off; off >>= 1) s += __shfl_down_sync(0xffffffffu, s, off);
    if (lane == 0) {
        float v = BNS * fg2[o] * (s + fb2[o]) + fbt2[o];
        g_y2[gw] = (v > 0.f) ? v : SLOPE * v;
    }
}

__global__ void fc3_kernel(const float* __restrict__ fw3, const float* __restrict__ fb3,
                           float* __restrict__ out) {
    int gw = threadIdx.x >> 5;
    int lane = threadIdx.x & 31;
    if (gw >= B * 3) return;
    int b = gw / 3, o = gw % 3;
    const float* h = g_y2 + b * 256;
    const float* wr = fw3 + (size_t)o * 256;
    float s = 0.f;
    for (int c = lane; c < 256; c += 32) s += h[c] * wr[c];
#pragma unroll
    for (int off = 16; off; off >>= 1) s += __shfl_down_sync(0xffffffffu, s, off);
    if (lane == 0) out[gw] = s + fb3[o];
}

// ---------------- launch ----------------
extern "C" void kernel_launch(void* const* d_in, const int* in_sizes, int n_in,
                              void* d_out, int out_size) {
    const float* points = (const float*)d_in[0];
    const float* w1 = (const float*)d_in[2];
    const float* g1 = (const float*)d_in[3];
    const float* b1 = (const float*)d_in[4];
    const float* w2 = (const float*)d_in[5];
    const float* g2 = (const float*)d_in[6];
    const float* b2 = (const float*)d_in[7];
    const float* w3 = (const float*)d_in[8];
    const float* g3 = (const float*)d_in[9];
    const float* b3 = (const float*)d_in[10];
    const float* w4 = (const float*)d_in[11];
    const float* g4 = (const float*)d_in[12];
    const float* b4 = (const float*)d_in[13];
    const float* w5 = (const float*)d_in[14];
    const float* g5 = (const float*)d_in[15];
    const float* b5 = (const float*)d_in[16];
    const float* fw1 = (const float*)d_in[17];
    const float* fg1 = (const float*)d_in[18];
    const float* fbt1 = (const float*)d_in[19];
    const float* fw2 = (const float*)d_in[20];
    const float* fb2 = (const float*)d_in[21];
    const float* fg2 = (const float*)d_in[22];
    const float* fbt2 = (const float*)d_in[23];
    const float* fw3 = (const float*)d_in[24];
    const float* fb3 = (const float*)d_in[25];
    float* out = (float*)d_out;

    int sm1 = 64 * 16 + 2 * 32 * 16 + 64 * 33 * 4;
    int merge1 = 64 * 4 * K * 8;
    if (merge1 > sm1) sm1 = merge1;
    int sm64  = (64 * 128 + 64 * 128 + 128 + 128 * 132) * 4;
    int sm128 = (128 * 128 + 128 * 128 + 128 + 128 * 132) * 4;
    int sm5   = 16384 * 4;
    static bool attr_done = false;
    if (!attr_done) {
        cudaFuncSetAttribute(knn1_kernel,      cudaFuncAttributeMaxDynamicSharedMemorySize, sm1);
        cudaFuncSetAttribute(knn2_kernel<64>,  cudaFuncAttributeMaxDynamicSharedMemorySize, sm64);
        cudaFuncSetAttribute(knn2_kernel<128>, cudaFuncAttributeMaxDynamicSharedMemorySize, sm128);
        cudaFuncSetAttribute(gemm5_kernel,     cudaFuncAttributeMaxDynamicSharedMemorySize, sm5);
        attr_done = true;
    }

    // ---- EdgeConv 1 (D=3, O=64) -> cat cols [0,64); edgemax writes sq for L2
    knn1_kernel<<<dim3(N / 64, B), 256, sm1>>>(points);                       // idx 0
    gemm_kernel<4><<<dim3(BN / 64, 2), 256>>>(points, 0, 3, w1, 3, 64, 128);  // idx 1
    edgemax_kernel<<<BN, 64>>>(g1, b1, 64, 0);                                // idx 2

    // ---- EdgeConv 2 (D=64, O=64) -> cat cols [64,128)
    knn2_kernel<64><<<dim3(N / 128, B), 256, sm64>>>(0);                      // idx 3 (profiled)
    gemm_kernel<64><<<dim3(BN / 64, 2), 256>>>(nullptr, 0, 512, w2, 64, 64, 128);
    edgemax_kernel<<<BN, 64>>>(g2, b2, 64, 64);

    // ---- EdgeConv 3 (D=64, O=128) -> cat cols [128,256)
    knn2_kernel<64><<<dim3(N / 128, B), 256, sm64>>>(64);
    gemm_kernel<64><<<dim3(BN / 64, 4), 256>>>(nullptr, 64, 512, w3, 64, 128, 256);
    edgemax_kernel<<<BN, 128>>>(g3, b3, 128, 128);

    // ---- EdgeConv 4 (D=128, O=256) -> cat cols [256,512)
    knn2_kernel<128><<<dim3(N / 128, B), 256, sm128>>>(128);
    gemm_kernel<128><<<dim3(BN / 64, 8), 256>>>(nullptr, 128, 512, w4, 128, 256, 512);
    edgemax_kernel<<<BN, 256>>>(g4, b4, 256, 256);

    // ---- w5 GEMM + bn + lrelu + row-block max
    prep_w5t_kernel<<<(512 * 1024 + 255) / 256, 256>>>(w5);
    gemm5_kernel<<<dim3(BN / 128, 8), 256, sm5>>>(g5, b5);
    maxreduce_kernel<<<(B * 1024 + 255) / 256, 256>>>();

    // ---- MLP head (warp per output)
    fc1_kernel<<<(B * 512 * 32 + 255) / 256, 256>>>(fw1, fg1, fbt1);
    fc2_kernel<<<(B * 256 * 32 + 255) / 256, 256>>>(fw2, fb2, fg2, fbt2);
    fc3_kernel<<<1, 384>>>(fw3, fb3, out);
}

// round 7
// speedup vs baseline: 1.5643x; 1.5643x over previous
#include <cuda_runtime.h>
#include <cstdint>

#define DEVINL __device__ __forceinline__

constexpr int B = 4, N = 4096, K = 10, BN = B * N;
constexpr float SLOPE = 0.2f;
constexpr float BNS = 0.9999950000374997f; // 1/sqrt(1+1e-5)
constexpr float NEG_INF = -3.4e38f;

DEVINL void fma2(unsigned long long& acc, unsigned long long a, unsigned long long b) {
    asm("fma.rn.f32x2 %0, %1, %2, %0;" : "+l"(acc) : "l"(a), "l"(b));
}
DEVINL float f2sum(unsigned long long v) {
    float2 f = *reinterpret_cast<float2*>(&v);
    return f.x + f.y;
}
struct U64x2 { unsigned long long a, b; };
DEVINL U64x2 asu64x2(const float4& v) {
    U64x2 r;
    r.a = *reinterpret_cast<const unsigned long long*>(&v.x);
    r.b = *reinterpret_cast<const unsigned long long*>(&v.z);
    return r;
}

// ---------------- scratch ----------------
__device__ float g_cat[BN * 512];
__device__ float g_AC[BN * 512];
__device__ float g_sq[BN];
__device__ int   g_knn[BN * K];
__device__ float g_wc[512 * 128];
__device__ float g_part[256 * 1024];
__device__ float g_h0[B * 1024];
__device__ float g_y1[B * 512];
__device__ float g_y2[B * 256];

// ================= layer-1 kNN (D=3), inline ||c||^2 =================
__global__ void __launch_bounds__(256) knn1_kernel(const float* __restrict__ x) {
    constexpr int CR4 = 32;
    extern __shared__ __align__(16) char smem[];
    float4* Q4 = (float4*)smem;
    float4* C4 = (float4*)(smem + 64 * 16);
    float*  Ss = (float*)(smem + 64 * 16 + 2 * CR4 * 16);
    float*  Mv = (float*)smem;
    int*    Mi = (int*)(smem + 64 * 4 * K * 4);

    int tid = threadIdx.x;
    int tx = tid & 15, ty = tid >> 4;
    int rq = tid & 63, rs = tid >> 6;
    int b = blockIdx.y, qbase = blockIdx.x * 64;
    const float* xb = x + (size_t)b * N * 3;
    int qglob = qbase + rq;

    float lv[K]; int li[K];
#pragma unroll
    for (int j = 0; j < K; ++j) { lv[j] = NEG_INF; li[j] = 0x7fffffff; }

    for (int i = tid; i < 64; i += 256) {
        const float* p = xb + (size_t)(qbase + i) * 3;
        Q4[i] = make_float4(p[0], p[1], p[2], 0.f);
    }

    float4 creg;
    auto load_c = [&](int cb) {
        if (tid < 32) {
            const float* p = xb + (size_t)(cb + tid) * 3;
            creg = make_float4(p[0], p[1], p[2], 0.f);
        }
    };
    load_c(0);

    for (int cb = 0; cb < N; cb += 32) {
        int buf = (cb >> 5) & 1;
        if (tid < 32) C4[buf * CR4 + tid] = creg;
        if (cb + 32 < N) load_c(cb + 32);
        __syncthreads();

        const float4* Cb = C4 + buf * CR4;
        U64x2 qv[4], cv[2];
#pragma unroll
        for (int qi = 0; qi < 4; ++qi) qv[qi] = asu64x2(Q4[ty + 16 * qi]);
#pragma unroll
        for (int ci = 0; ci < 2; ++ci) cv[ci] = asu64x2(Cb[tx + 16 * ci]);

        float sc[2];
#pragma unroll
        for (int ci = 0; ci < 2; ++ci) {
            unsigned long long a = 0ull;
            fma2(a, cv[ci].a, cv[ci].a);
            fma2(a, cv[ci].b, cv[ci].b);
            sc[ci] = f2sum(a);
        }

        unsigned long long acc2[4][2];
#pragma unroll
        for (int qi = 0; qi < 4; ++qi) { acc2[qi][0] = 0ull; acc2[qi][1] = 0ull; }
#pragma unroll
        for (int qi = 0; qi < 4; ++qi)
#pragma unroll
            for (int ci = 0; ci < 2; ++ci) {
                fma2(acc2[qi][ci], qv[qi].a, cv[ci].a);
                fma2(acc2[qi][ci], qv[qi].b, cv[ci].b);
            }
#pragma unroll
        for (int qi = 0; qi < 4; ++qi) {
            Ss[(ty + 16 * qi) * 33 + tx]      = 2.f * f2sum(acc2[qi][0]) - sc[0];
            Ss[(ty + 16 * qi) * 33 + tx + 16] = 2.f * f2sum(acc2[qi][1]) - sc[1];
        }
        __syncthreads();

#pragma unroll
        for (int j = 0; j < 8; ++j) {
            int c = cb + rs * 8 + j;
            float v = Ss[rq * 33 + rs * 8 + j];
            if (c != qglob) {
                if (v > lv[K - 1] || (v == lv[K - 1] && c < li[K - 1])) {
                    float cvv = v; int cid = c;
#pragma unroll
                    for (int t = 0; t < K; ++t) {
                        bool better = (cvv > lv[t]) || (cvv == lv[t] && cid < li[t]);
                        float tv = lv[t]; int ti = li[t];
                        if (better) { lv[t] = cvv; li[t] = cid; cvv = tv; cid = ti; }
                    }
                }
            }
        }
        __syncthreads();
    }
    __syncthreads();

#pragma unroll
    for (int j = 0; j < K; ++j) {
        Mv[(rq * 4 + rs) * K + j] = lv[j];
        Mi[(rq * 4 + rs) * K + j] = li[j];
    }
    __syncthreads();
    if (tid < 64) {
        int h[4] = {0, 0, 0, 0};
        int base = tid * 4 * K;
        int* out = g_knn + (size_t)(b * N + qbase + tid) * K;
        for (int j = 0; j < K; ++j) {
            float bv = NEG_INF; int bi = 0x7fffffff; int bs = 0;
#pragma unroll
            for (int s = 0; s < 4; ++s) {
                if (h[s] < K) {
                    float v = Mv[base + s * K + h[s]];
                    int   i = Mi[base + s * K + h[s]];
                    if (v > bv || (v == bv && i < bi)) { bv = v; bi = i; bs = s; }
                }
            }
            h[bs]++;
            out[j] = bi;
        }
    }
}

// ================= kNN for D in {64,128}: R4-proven 64q x 32c tile =========
template<int DPAD>
__global__ void __launch_bounds__(256) knn_kernel(int xoff) {
    constexpr int R4  = DPAD / 4;
    constexpr int SWM = 7;
    constexpr int CR4 = 32 * R4;
    constexpr int NL  = (CR4 + 255) / 256;
    extern __shared__ __align__(16) char smem[];
    float4* Q4 = (float4*)smem;
    float4* C4 = (float4*)(smem + (size_t)64 * R4 * 16);
    float*  Ss = (float*)(smem + (size_t)64 * R4 * 16 + (size_t)2 * CR4 * 16);
    float*  Mv = (float*)smem;
    int*    Mi = (int*)(smem + 64 * 4 * K * 4);

    const float* x = g_cat + xoff;
    int tid = threadIdx.x;
    int tx = tid & 15, ty = tid >> 4;
    int rq = tid & 63, rs = tid >> 6;
    int b = blockIdx.y, qbase = blockIdx.x * 64;
    const float* xb  = x + (size_t)b * N * 512;
    const float* sqb = g_sq + b * N;
    int qglob = qbase + rq;

    float lv[K]; int li[K];
#pragma unroll
    for (int j = 0; j < K; ++j) { lv[j] = NEG_INF; li[j] = 0x7fffffff; }

    for (int i = tid; i < 64 * R4; i += 256) {
        int row = i / R4, dv = i % R4;
        Q4[row * R4 + (dv ^ (row & SWM))] =
            *(const float4*)(xb + (size_t)(qbase + row) * 512 + dv * 4);
    }

    float4 creg[NL];
    auto load_c = [&](int cb) {
#pragma unroll
        for (int l = 0; l < NL; ++l) {
            int i = tid + l * 256;
            if ((CR4 % 256 == 0) || i < CR4) {
                int row = i / R4, dv = i % R4;
                creg[l] = *(const float4*)(xb + (size_t)(cb + row) * 512 + dv * 4);
            }
        }
    };
    auto store_c = [&](int buf) {
#pragma unroll
        for (int l = 0; l < NL; ++l) {
            int i = tid + l * 256;
            if ((CR4 % 256 == 0) || i < CR4) {
                int row = i / R4, dv = i % R4;
                C4[buf * CR4 + row * R4 + (dv ^ (row & SWM))] = creg[l];
            }
        }
    };

    load_c(0);

    for (int cb = 0; cb < N; cb += 32) {
        int buf = (cb >> 5) & 1;
        store_c(buf);
        if (cb + 32 < N) load_c(cb + 32);
        float sc0 = sqb[cb + tx], sc1 = sqb[cb + tx + 16];
        __syncthreads();

        unsigned long long acc2[4][2];
#pragma unroll
        for (int qi = 0; qi < 4; ++qi) { acc2[qi][0] = 0ull; acc2[qi][1] = 0ull; }
        const float4* Cb = C4 + buf * CR4;
#pragma unroll
        for (int dv = 0; dv < R4; ++dv) {
            U64x2 qv[4], cv[2];
#pragma unroll
            for (int qi = 0; qi < 4; ++qi)
                qv[qi] = asu64x2(Q4[(ty + 16 * qi) * R4 + (dv ^ (ty & SWM))]);
#pragma unroll
            for (int ci = 0; ci < 2; ++ci)
                cv[ci] = asu64x2(Cb[(tx + 16 * ci) * R4 + (dv ^ (tx & SWM))]);
#pragma unroll
            for (int qi = 0; qi < 4; ++qi)
#pragma unroll
                for (int ci = 0; ci < 2; ++ci) {
                    fma2(acc2[qi][ci], qv[qi].a, cv[ci].a);
                    fma2(acc2[qi][ci], qv[qi].b, cv[ci].b);
                }
        }
#pragma unroll
        for (int qi = 0; qi < 4; ++qi) {
            Ss[(ty + 16 * qi) * 33 + tx]      = 2.f * f2sum(acc2[qi][0]) - sc0;
            Ss[(ty + 16 * qi) * 33 + tx + 16] = 2.f * f2sum(acc2[qi][1]) - sc1;
        }
        __syncthreads();

#pragma unroll
        for (int j = 0; j < 8; ++j) {
            int c = cb + rs * 8 + j;
            float v = Ss[rq * 33 + rs * 8 + j];
            if (c != qglob) {
                if (v > lv[K - 1] || (v == lv[K - 1] && c < li[K - 1])) {
                    float cvv = v; int cid = c;
#pragma unroll
                    for (int t = 0; t < K; ++t) {
                        bool better = (cvv > lv[t]) || (cvv == lv[t] && cid < li[t]);
                        float tv = lv[t]; int ti = li[t];
                        if (better) { lv[t] = cvv; li[t] = cid; cvv = tv; cid = ti; }
                    }
                }
            }
        }
    }
    __syncthreads();

#pragma unroll
    for (int j = 0; j < K; ++j) {
        Mv[(rq * 4 + rs) * K + j] = lv[j];
        Mi[(rq * 4 + rs) * K + j] = li[j];
    }
    __syncthreads();
    if (tid < 64) {
        int h[4] = {0, 0, 0, 0};
        int base = tid * 4 * K;
        int* out = g_knn + (size_t)(b * N + qbase + tid) * K;
        for (int j = 0; j < K; ++j) {
            float bv = NEG_INF; int bi = 0x7fffffff; int bs = 0;
#pragma unroll
            for (int s = 0; s < 4; ++s) {
                if (h[s] < K) {
                    float v = Mv[base + s * K + h[s]];
                    int   i = Mi[base + s * K + h[s]];
                    if (v > bv || (v == bv && i < bi)) { bv = v; bi = i; bs = s; }
                }
            }
            h[bs]++;
            out[j] = bi;
        }
    }
}

// ---------------- layer-1 AC GEMM with inline w1 prep (D=3) ----------------
__global__ void __launch_bounds__(256) gemm1_kernel(const float* __restrict__ x,
                                                    const float* __restrict__ w1) {
    __shared__ float4 Xs[64];
    __shared__ float4 Ws[64];
    int tid = threadIdx.x, tx = tid & 15, ty = tid >> 4;
    int rowbase = blockIdx.x * 64, colbase = blockIdx.y * 64;

    if (tid < 64) {
        const float* p = x + (size_t)(rowbase + tid) * 3;
        Xs[tid] = make_float4(p[0], p[1], p[2], 0.f);
        int cr = colbase + tid;
        float vv[3];
#pragma unroll
        for (int e = 0; e < 3; ++e) {
            if (cr < 64) vv[e] = w1[cr * 6 + e];
            else { int o = cr - 64; vv[e] = w1[o * 6 + 3 + e] - w1[o * 6 + e]; }
        }
        Ws[tid] = make_float4(vv[0], vv[1], vv[2], 0.f);
    }
    __syncthreads();

    unsigned long long acc2[4][4];
#pragma unroll
    for (int qi = 0; qi < 4; ++qi)
#pragma unroll
        for (int ci = 0; ci < 4; ++ci) acc2[qi][ci] = 0ull;
    U64x2 xv[4], wv[4];
#pragma unroll
    for (int qi = 0; qi < 4; ++qi) xv[qi] = asu64x2(Xs[ty + 16 * qi]);
#pragma unroll
    for (int ci = 0; ci < 4; ++ci) wv[ci] = asu64x2(Ws[tx + 16 * ci]);
#pragma unroll
    for (int qi = 0; qi < 4; ++qi)
#pragma unroll
        for (int ci = 0; ci < 4; ++ci) {
            fma2(acc2[qi][ci], xv[qi].a, wv[ci].a);
            fma2(acc2[qi][ci], xv[qi].b, wv[ci].b);
        }
#pragma unroll
    for (int qi = 0; qi < 4; ++qi)
#pragma unroll
        for (int ci = 0; ci < 4; ++ci)
            g_AC[(size_t)(rowbase + ty + 16 * qi) * 128 + colbase + tx + 16 * ci] =
                f2sum(acc2[qi][ci]);
}

// ---------------- weight prep: wc = [w1 ; w2-w1] padded to DPAD ----------------
__global__ void prep_wc_kernel(const float* __restrict__ w, int O, int D, int DPAD) {
    int i = blockIdx.x * blockDim.x + threadIdx.x;
    int total = 2 * O * DPAD;
    if (i >= total) return;
    int r = i / DPAD, d = i % DPAD;
    float v = 0.f;
    if (d < D) {
        if (r < O) v = w[r * 2 * D + d];
        else { int o = r - O; v = w[o * 2 * D + D + d] - w[o * 2 * D + d]; }
    }
    g_wc[i] = v;
}

// ---------------- R4 register-tiled GEMM (64x64), optional w5 epilogue -----
template<int DPAD, bool W5MAX>
__global__ void __launch_bounds__(256) gemm_kernel(
    int xoff, const float* __restrict__ wext, int ldw, int ldo,
    const float* __restrict__ gg, const float* __restrict__ bb)
{
    constexpr int DC  = (DPAD < 32) ? DPAD : 32;
    constexpr int RC  = DC / 4;
    constexpr int SWM = (RC >= 8) ? 7 : 0;
    constexpr int NCH = DPAD / DC;
    constexpr int TR4 = 64 * RC;
    constexpr int NL  = (TR4 + 255) / 256;
    __shared__ float4 Xs[2 * TR4];
    __shared__ float4 Ws[2 * TR4];
    const float* x = g_cat + xoff;
    const float* w = W5MAX ? wext : g_wc;
    int tid = threadIdx.x, tx = tid & 15, ty = tid >> 4;
    int rowbase = blockIdx.x * 64, colbase = blockIdx.y * 64;
    unsigned long long acc2[4][4];
#pragma unroll
    for (int qi = 0; qi < 4; ++qi)
#pragma unroll
        for (int ci = 0; ci < 4; ++ci) acc2[qi][ci] = 0ull;

    float4 xreg[NL], wreg[NL];
    auto load_xw = [&](int ch) {
        int d0 = ch * DC;
#pragma unroll
        for (int l = 0; l < NL; ++l) {
            int i = tid + l * 256;
            if ((TR4 % 256 == 0) || i < TR4) {
                int r = i / RC, dv = i % RC;
                xreg[l] = *(const float4*)(x + (size_t)(rowbase + r) * 512 + d0 + 4 * dv);
                wreg[l] = *(const float4*)(w + (size_t)(colbase + r) * ldw + d0 + 4 * dv);
            }
        }
    };
    auto store_xw = [&](int buf) {
#pragma unroll
        for (int l = 0; l < NL; ++l) {
            int i = tid + l * 256;
            if ((TR4 % 256 == 0) || i < TR4) {
                int r = i / RC, dv = i % RC;
                Xs[buf * TR4 + r * RC + (dv ^ (r & SWM))] = xreg[l];
                Ws[buf * TR4 + r * RC + (dv ^ (r & SWM))] = wreg[l];
            }
        }
    };

    load_xw(0);
    for (int ch = 0; ch < NCH; ++ch) {
        int buf = ch & 1;
        store_xw(buf);
        if (ch + 1 < NCH) load_xw(ch + 1);
        __syncthreads();
        const float4* Xb = Xs + buf * TR4;
        const float4* Wb = Ws + buf * TR4;
#pragma unroll
        for (int dv = 0; dv < RC; ++dv) {
            U64x2 xv[4], wv[4];
#pragma unroll
            for (int qi = 0; qi < 4; ++qi)
                xv[qi] = asu64x2(Xb[(ty + 16 * qi) * RC + (dv ^ (ty & SWM))]);
#pragma unroll
            for (int ci = 0; ci < 4; ++ci)
                wv[ci] = asu64x2(Wb[(tx + 16 * ci) * RC + (dv ^ (tx & SWM))]);
#pragma unroll
            for (int qi = 0; qi < 4; ++qi)
#pragma unroll
                for (int ci = 0; ci < 4; ++ci) {
                    fma2(acc2[qi][ci], xv[qi].a, wv[ci].a);
                    fma2(acc2[qi][ci], xv[qi].b, wv[ci].b);
                }
        }
        __syncthreads();
    }

    if constexpr (!W5MAX) {
#pragma unroll
        for (int qi = 0; qi < 4; ++qi)
#pragma unroll
            for (int ci = 0; ci < 4; ++ci)
                g_AC[(size_t)(rowbase + ty + 16 * qi) * ldo + colbase + tx + 16 * ci] =
                    f2sum(acc2[qi][ci]);
    } else {
        float cm[4];
#pragma unroll
        for (int ci = 0; ci < 4; ++ci) {
            int col = colbase + tx + 16 * ci;
            float g = BNS * gg[col], be = bb[col];
            float m = NEG_INF;
#pragma unroll
            for (int qi = 0; qi < 4; ++qi) {
                float v = g * f2sum(acc2[qi][ci]) + be;
                v = (v > 0.f) ? v : SLOPE * v;
                m = fmaxf(m, v);
            }
            cm[ci] = m;
        }
        float* R = (float*)Xs;
#pragma unroll
        for (int ci = 0; ci < 4; ++ci) R[ty * 64 + tx + 16 * ci] = cm[ci];
        __syncthreads();
        if (tid < 64) {
            float m = R[tid];
#pragma unroll
            for (int t = 1; t < 16; ++t) m = fmaxf(m, R[t * 64 + tid]);
            g_part[(size_t)blockIdx.x * 1024 + colbase + tid] = m;
        }
    }
}

// ---------------- gather + bn + lrelu + max, fused next-layer sqnorm -------
__global__ void edgemax_kernel(const float* __restrict__ gamma, const float* __restrict__ beta,
                               int O, int catoff) {
    int n = blockIdx.x;
    int o = threadIdx.x;
    int b = n >> 12;
    __shared__ int sidx[K];
    __shared__ float ps[8];
    if (o < K) sidx[o] = g_knn[(size_t)n * K + o];
    __syncthreads();
    int twoO = 2 * O;
    float cterm = g_AC[(size_t)n * twoO + O + o];
    float g = BNS * gamma[o], be = beta[o];
    int base = b << 12;
    float m = NEG_INF;
#pragma unroll
    for (int j = 0; j < K; ++j) {
        float a = g_AC[(size_t)(base + sidx[j]) * twoO + o];
        float v = g * (a + cterm) + be;
        v = (v > 0.f) ? v : SLOPE * v;
        m = fmaxf(m, v);
    }
    g_cat[(size_t)n * 512 + catoff + o] = m;

    float p = m * m;
#pragma unroll
    for (int off = 16; off; off >>= 1) p += __shfl_down_sync(0xffffffffu, p, off);
    if ((o & 31) == 0) ps[o >> 5] = p;
    __syncthreads();
    if (o == 0) {
        float s = 0.f;
        int nw = O >> 5;
        for (int w = 0; w < nw; ++w) s += ps[w];
        g_sq[n] = s;
    }
}

// ---------------- final max reduce + warp-per-output MLP head -------------
__global__ void maxreduce_kernel() {
    int i = blockIdx.x * blockDim.x + threadIdx.x;
    if (i >= B * 1024) return;
    int b = i / 1024, o = i % 1024;
    float m = NEG_INF;
    for (int j = 0; j < 64; ++j)
        m = fmaxf(m, g_part[(size_t)(b * 64 + j) * 1024 + o]);
    g_h0[i] = m;
}

__global__ void fc1_kernel(const float* __restrict__ fw1, const float* __restrict__ fg1,
                           const float* __restrict__ fbt1) {
    int gw = (blockIdx.x * blockDim.x + threadIdx.x) >> 5;
    int lane = threadIdx.x & 31;
    if (gw >= B * 512) return;
    int b = gw >> 9, o = gw & 511;
    const float* h = g_h0 + b * 1024;
    const float* wr = fw1 + (size_t)o * 1024;
    float s = 0.f;
    for (int c = lane; c < 1024; c += 32) s += h[c] * wr[c];
#pragma unroll
    for (int off = 16; off; off >>= 1) s += __shfl_down_sync(0xffffffffu, s, off);
    if (lane == 0) {
        float v = BNS * fg1[o] * s + fbt1[o];
        g_y1[gw] = (v > 0.f) ? v : SLOPE * v;
    }
}

__global__ void fc2_kernel(const float* __restrict__ fw2, const float* __restrict__ fb2,
                           const float* __restrict__ fg2, const float* __restrict__ fbt2) {
    int gw = (blockIdx.x * blockDim.x + threadIdx.x) >> 5;
    int lane = threadIdx.x & 31;
    if (gw >= B * 256) return;
    int b = gw >> 8, o = gw & 255;
    const float* h = g_y1 + b * 512;
    const float* wr = fw2 + (size_t)o * 512;
    float s = 0.f;
    for (int c = lane; c < 512; c += 32) s += h[c] * wr[c];
#pragma unroll
    for (int off = 16; off; off >>= 1) s += __shfl_down_sync(0xffffffffu, s, off);
    if (lane == 0) {
        float v = BNS * fg2[o] * (s + fb2[o]) + fbt2[o];
        g_y2[gw] = (v > 0.f) ? v : SLOPE * v;
    }
}

__global__ void fc3_kernel(const float* __restrict__ fw3, const float* __restrict__ fb3,
                           float* __restrict__ out) {
    int gw = threadIdx.x >> 5;
    int lane = threadIdx.x & 31;
    if (gw >= B * 3) return;
    int b = gw / 3, o = gw % 3;
    const float* h = g_y2 + b * 256;
    const float* wr = fw3 + (size_t)o * 256;
    float s = 0.f;
    for (int c = lane; c < 256; c += 32) s += h[c] * wr[c];
#pragma unroll
    for (int off = 16; off; off >>= 1) s += __shfl_down_sync(0xffffffffu, s, off);
    if (lane == 0) out[gw] = s + fb3[o];
}

// ---------------- launch ----------------
static int knn_smem_bytes(int R4) {
    int s = 64 * R4 * 16 + 2 * 32 * R4 * 16 + 64 * 33 * 4;
    int merge = 64 * 4 * K * 8;
    return s > merge ? s : merge;
}

extern "C" void kernel_launch(void* const* d_in, const int* in_sizes, int n_in,
                              void* d_out, int out_size) {
    const float* points = (const float*)d_in[0];
    const float* w1 = (const float*)d_in[2];
    const float* g1 = (const float*)d_in[3];
    const float* b1 = (const float*)d_in[4];
    const float* w2 = (const float*)d_in[5];
    const float* g2 = (const float*)d_in[6];
    const float* b2 = (const float*)d_in[7];
    const float* w3 = (const float*)d_in[8];
    const float* g3 = (const float*)d_in[9];
    const float* b3 = (const float*)d_in[10];
    const float* w4 = (const float*)d_in[11];
    const float* g4 = (const float*)d_in[12];
    const float* b4 = (const float*)d_in[13];
    const float* w5 = (const float*)d_in[14];
    const float* g5 = (const float*)d_in[15];
    const float* b5 = (const float*)d_in[16];
    const float* fw1 = (const float*)d_in[17];
    const float* fg1 = (const float*)d_in[18];
    const float* fbt1 = (const float*)d_in[19];
    const float* fw2 = (const float*)d_in[20];
    const float* fb2 = (const float*)d_in[21];
    const float* fg2 = (const float*)d_in[22];
    const float* fbt2 = (const float*)d_in[23];
    const float* fw3 = (const float*)d_in[24];
    const float* fb3 = (const float*)d_in[25];
    float* out = (float*)d_out;

    int sm1 = 64 * 16 + 2 * 32 * 16 + 64 * 33 * 4;
    int merge1 = 64 * 4 * K * 8;
    if (merge1 > sm1) sm1 = merge1;
    int sm16 = knn_smem_bytes(16);
    int sm32 = knn_smem_bytes(32);
    static bool attr_done = false;
    if (!attr_done) {
        cudaFuncSetAttribute(knn1_kernel,     cudaFuncAttributeMaxDynamicSharedMemorySize, sm1);
        cudaFuncSetAttribute(knn_kernel<64>,  cudaFuncAttributeMaxDynamicSharedMemorySize, sm16);
        cudaFuncSetAttribute(knn_kernel<128>, cudaFuncAttributeMaxDynamicSharedMemorySize, sm32);
        attr_done = true;
    }

    dim3 knngrid(N / 64, B);

    // ---- EdgeConv 1 (D=3, O=64) -> cat cols [0,64)
    knn1_kernel<<<knngrid, 256, sm1>>>(points);                       // idx 0
    gemm1_kernel<<<dim3(BN / 64, 2), 256>>>(points, w1);              // idx 1
    edgemax_kernel<<<BN, 64>>>(g1, b1, 64, 0);                        // idx 2

    // ---- EdgeConv 2 (D=64, O=64) -> cat cols [64,128)
    knn_kernel<64><<<knngrid, 256, sm16>>>(0);                        // idx 3 (profiled)
    prep_wc_kernel<<<(2 * 64 * 64 + 255) / 256, 256>>>(w2, 64, 64, 64);
    gemm_kernel<64, false><<<dim3(BN / 64, 2), 256>>>(0, nullptr, 64, 128, nullptr, nullptr);
    edgemax_kernel<<<BN, 64>>>(g2, b2, 64, 64);

    // ---- EdgeConv 3 (D=64, O=128) -> cat cols [128,256)
    knn_kernel<64><<<knngrid, 256, sm16>>>(64);
    prep_wc_kernel<<<(2 * 128 * 64 + 255) / 256, 256>>>(w3, 128, 64, 64);
    gemm_kernel<64, false><<<dim3(BN / 64, 4), 256>>>(64, nullptr, 64, 256, nullptr, nullptr);
    edgemax_kernel<<<BN, 128>>>(g3, b3, 128, 128);

    // ---- EdgeConv 4 (D=128, O=256) -> cat cols [256,512)
    knn_kernel<128><<<knngrid, 256, sm32>>>(128);
    prep_wc_kernel<<<(2 * 256 * 128 + 255) / 256, 256>>>(w4, 256, 128, 128);
    gemm_kernel<128, false><<<dim3(BN / 64, 8), 256>>>(128, nullptr, 128, 512, nullptr, nullptr);
    edgemax_kernel<<<BN, 256>>>(g4, b4, 256, 256);

    // ---- w5 GEMM (16384x512x1024) + bn + lrelu + row-block max
    gemm_kernel<512, true><<<dim3(BN / 64, 16), 256>>>(0, w5, 512, 0, g5, b5);
    maxreduce_kernel<<<(B * 1024 + 255) / 256, 256>>>();

    // ---- MLP head (warp per output)
    fc1_kernel<<<(B * 512 * 32 + 255) / 256, 256>>>(fw1, fg1, fbt1);
    fc2_kernel<<<(B * 256 * 32 + 255) / 256, 256>>>(fw2, fb2, fg2, fbt2);
    fc3_kernel<<<1, 384>>>(fw3, fb3, out);
}

// round 8
// speedup vs baseline: 1.6631x; 1.0632x over previous
#include <cuda_runtime.h>
#include <cstdint>

#define DEVINL __device__ __forceinline__

constexpr int B = 4, N = 4096, K = 10, BN = B * N;
constexpr int NSPLIT = 4, ZLEN = N / NSPLIT;
constexpr float SLOPE = 0.2f;
constexpr float BNS = 0.9999950000374997f; // 1/sqrt(1+1e-5)
constexpr float NEG_INF = -3.4e38f;

DEVINL void fma2(unsigned long long& acc, unsigned long long a, unsigned long long b) {
    asm("fma.rn.f32x2 %0, %1, %2, %0;" : "+l"(acc) : "l"(a), "l"(b));
}
DEVINL float f2sum(unsigned long long v) {
    float2 f = *reinterpret_cast<float2*>(&v);
    return f.x + f.y;
}
struct U64x2 { unsigned long long a, b; };
DEVINL U64x2 asu64x2(const float4& v) {
    U64x2 r;
    r.a = *reinterpret_cast<const unsigned long long*>(&v.x);
    r.b = *reinterpret_cast<const unsigned long long*>(&v.z);
    return r;
}

// ---------------- scratch ----------------
__device__ float g_cat[BN * 512];
__device__ float g_AC[BN * 512];
__device__ float g_sq[BN];
__device__ int   g_knn[BN * K];
__device__ float g_pkv[(size_t)BN * NSPLIT * K];
__device__ int   g_pki[(size_t)BN * NSPLIT * K];
__device__ float g_wc[512 * 128];
__device__ float g_part[256 * 1024];
__device__ float g_h0[B * 1024];
__device__ float g_y1[B * 512];
__device__ float g_y2[B * 256];

// ---------------- partial-list merge: NSPLIT sorted K-lists per query ------
__global__ void knnmerge_kernel() {
    int q = blockIdx.x * blockDim.x + threadIdx.x;
    if (q >= BN) return;
    const float* pv = g_pkv + (size_t)q * NSPLIT * K;
    const int*   pi = g_pki + (size_t)q * NSPLIT * K;
    int h[NSPLIT];
#pragma unroll
    for (int s = 0; s < NSPLIT; ++s) h[s] = 0;
    int* out = g_knn + (size_t)q * K;
#pragma unroll
    for (int j = 0; j < K; ++j) {
        float bv = NEG_INF; int bi = 0x7fffffff; int bs = 0;
#pragma unroll
        for (int s = 0; s < NSPLIT; ++s) {
            if (h[s] < K) {
                float v = pv[s * K + h[s]];
                int   i = pi[s * K + h[s]];
                if (v > bv || (v == bv && i < bi)) { bv = v; bi = i; bs = s; }
            }
        }
        h[bs]++;
        out[j] = bi;
    }
}

// ================= layer-1 kNN (D=3), candidate-split =================
__global__ void __launch_bounds__(256) knn1_kernel(const float* __restrict__ x) {
    constexpr int CR4 = 32;
    extern __shared__ __align__(16) char smem[];
    float4* Q4 = (float4*)smem;
    float4* C4 = (float4*)(smem + 64 * 16);
    float*  Ss = (float*)(smem + 64 * 16 + 2 * CR4 * 16);
    float*  Mv = (float*)smem;
    int*    Mi = (int*)(smem + 64 * 4 * K * 4);

    int tid = threadIdx.x;
    int tx = tid & 15, ty = tid >> 4;
    int rq = tid & 63, rs = tid >> 6;
    int b = blockIdx.y, qbase = blockIdx.x * 64;
    int cb0 = blockIdx.z * ZLEN;
    const float* xb = x + (size_t)b * N * 3;
    int qglob = qbase + rq;

    float lv[K]; int li[K];
#pragma unroll
    for (int j = 0; j < K; ++j) { lv[j] = NEG_INF; li[j] = 0x7fffffff; }

    for (int i = tid; i < 64; i += 256) {
        const float* p = xb + (size_t)(qbase + i) * 3;
        Q4[i] = make_float4(p[0], p[1], p[2], 0.f);
    }

    float4 creg;
    auto load_c = [&](int cb) {
        if (tid < 32) {
            const float* p = xb + (size_t)(cb + tid) * 3;
            creg = make_float4(p[0], p[1], p[2], 0.f);
        }
    };
    load_c(cb0);

    for (int cb = cb0; cb < cb0 + ZLEN; cb += 32) {
        int buf = ((cb - cb0) >> 5) & 1;
        if (tid < 32) C4[buf * CR4 + tid] = creg;
        if (cb + 32 < cb0 + ZLEN) load_c(cb + 32);
        __syncthreads();

        const float4* Cb = C4 + buf * CR4;
        U64x2 qv[4], cv[2];
#pragma unroll
        for (int qi = 0; qi < 4; ++qi) qv[qi] = asu64x2(Q4[ty + 16 * qi]);
#pragma unroll
        for (int ci = 0; ci < 2; ++ci) cv[ci] = asu64x2(Cb[tx + 16 * ci]);

        float sc[2];
#pragma unroll
        for (int ci = 0; ci < 2; ++ci) {
            unsigned long long a = 0ull;
            fma2(a, cv[ci].a, cv[ci].a);
            fma2(a, cv[ci].b, cv[ci].b);
            sc[ci] = f2sum(a);
        }

        unsigned long long acc2[4][2];
#pragma unroll
        for (int qi = 0; qi < 4; ++qi) { acc2[qi][0] = 0ull; acc2[qi][1] = 0ull; }
#pragma unroll
        for (int qi = 0; qi < 4; ++qi)
#pragma unroll
            for (int ci = 0; ci < 2; ++ci) {
                fma2(acc2[qi][ci], qv[qi].a, cv[ci].a);
                fma2(acc2[qi][ci], qv[qi].b, cv[ci].b);
            }
#pragma unroll
        for (int qi = 0; qi < 4; ++qi) {
            Ss[(ty + 16 * qi) * 33 + tx]      = 2.f * f2sum(acc2[qi][0]) - sc[0];
            Ss[(ty + 16 * qi) * 33 + tx + 16] = 2.f * f2sum(acc2[qi][1]) - sc[1];
        }
        __syncthreads();

#pragma unroll
        for (int j = 0; j < 8; ++j) {
            int c = cb + rs * 8 + j;
            float v = Ss[rq * 33 + rs * 8 + j];
            if (c != qglob) {
                if (v > lv[K - 1] || (v == lv[K - 1] && c < li[K - 1])) {
                    float cvv = v; int cid = c;
#pragma unroll
                    for (int t = 0; t < K; ++t) {
                        bool better = (cvv > lv[t]) || (cvv == lv[t] && cid < li[t]);
                        float tv = lv[t]; int ti = li[t];
                        if (better) { lv[t] = cvv; li[t] = cid; cvv = tv; cid = ti; }
                    }
                }
            }
        }
        __syncthreads();
    }
    __syncthreads();

#pragma unroll
    for (int j = 0; j < K; ++j) {
        Mv[(rq * 4 + rs) * K + j] = lv[j];
        Mi[(rq * 4 + rs) * K + j] = li[j];
    }
    __syncthreads();
    if (tid < 64) {
        int h[4] = {0, 0, 0, 0};
        int base = tid * 4 * K;
        float* pv = g_pkv + ((size_t)(b * N + qbase + tid) * NSPLIT + blockIdx.z) * K;
        int*   pi = g_pki + ((size_t)(b * N + qbase + tid) * NSPLIT + blockIdx.z) * K;
        for (int j = 0; j < K; ++j) {
            float bv = NEG_INF; int bi = 0x7fffffff; int bs = 0;
#pragma unroll
            for (int s = 0; s < 4; ++s) {
                if (h[s] < K) {
                    float v = Mv[base + s * K + h[s]];
                    int   i = Mi[base + s * K + h[s]];
                    if (v > bv || (v == bv && i < bi)) { bv = v; bi = i; bs = s; }
                }
            }
            h[bs]++;
            pv[j] = bv; pi[j] = bi;
        }
    }
}

// ================= kNN for D in {64,128}: 64q x 32c tile, candidate-split ===
template<int DPAD>
__global__ void __launch_bounds__(256) knn_kernel(int xoff) {
    constexpr int R4  = DPAD / 4;
    constexpr int SWM = 7;
    constexpr int CR4 = 32 * R4;
    constexpr int NL  = (CR4 + 255) / 256;
    extern __shared__ __align__(16) char smem[];
    float4* Q4 = (float4*)smem;
    float4* C4 = (float4*)(smem + (size_t)64 * R4 * 16);
    float*  Ss = (float*)(smem + (size_t)64 * R4 * 16 + (size_t)2 * CR4 * 16);
    float*  Mv = (float*)smem;
    int*    Mi = (int*)(smem + 64 * 4 * K * 4);

    const float* x = g_cat + xoff;
    int tid = threadIdx.x;
    int tx = tid & 15, ty = tid >> 4;
    int rq = tid & 63, rs = tid >> 6;
    int b = blockIdx.y, qbase = blockIdx.x * 64;
    int cb0 = blockIdx.z * ZLEN;
    const float* xb  = x + (size_t)b * N * 512;
    const float* sqb = g_sq + b * N;
    int qglob = qbase + rq;

    float lv[K]; int li[K];
#pragma unroll
    for (int j = 0; j < K; ++j) { lv[j] = NEG_INF; li[j] = 0x7fffffff; }

    for (int i = tid; i < 64 * R4; i += 256) {
        int row = i / R4, dv = i % R4;
        Q4[row * R4 + (dv ^ (row & SWM))] =
            *(const float4*)(xb + (size_t)(qbase + row) * 512 + dv * 4);
    }

    float4 creg[NL];
    auto load_c = [&](int cb) {
#pragma unroll
        for (int l = 0; l < NL; ++l) {
            int i = tid + l * 256;
            if ((CR4 % 256 == 0) || i < CR4) {
                int row = i / R4, dv = i % R4;
                creg[l] = *(const float4*)(xb + (size_t)(cb + row) * 512 + dv * 4);
            }
        }
    };
    auto store_c = [&](int buf) {
#pragma unroll
        for (int l = 0; l < NL; ++l) {
            int i = tid + l * 256;
            if ((CR4 % 256 == 0) || i < CR4) {
                int row = i / R4, dv = i % R4;
                C4[buf * CR4 + row * R4 + (dv ^ (row & SWM))] = creg[l];
            }
        }
    };

    load_c(cb0);

    for (int cb = cb0; cb < cb0 + ZLEN; cb += 32) {
        int buf = ((cb - cb0) >> 5) & 1;
        store_c(buf);
        if (cb + 32 < cb0 + ZLEN) load_c(cb + 32);
        float sc0 = sqb[cb + tx], sc1 = sqb[cb + tx + 16];
        __syncthreads();

        unsigned long long acc2[4][2];
#pragma unroll
        for (int qi = 0; qi < 4; ++qi) { acc2[qi][0] = 0ull; acc2[qi][1] = 0ull; }
        const float4* Cb = C4 + buf * CR4;
#pragma unroll
        for (int dv = 0; dv < R4; ++dv) {
            U64x2 qv[4], cv[2];
#pragma unroll
            for (int qi = 0; qi < 4; ++qi)
                qv[qi] = asu64x2(Q4[(ty + 16 * qi) * R4 + (dv ^ (ty & SWM))]);
#pragma unroll
            for (int ci = 0; ci < 2; ++ci)
                cv[ci] = asu64x2(Cb[(tx + 16 * ci) * R4 + (dv ^ (tx & SWM))]);
#pragma unroll
            for (int qi = 0; qi < 4; ++qi)
#pragma unroll
                for (int ci = 0; ci < 2; ++ci) {
                    fma2(acc2[qi][ci], qv[qi].a, cv[ci].a);
                    fma2(acc2[qi][ci], qv[qi].b, cv[ci].b);
                }
        }
#pragma unroll
        for (int qi = 0; qi < 4; ++qi) {
            Ss[(ty + 16 * qi) * 33 + tx]      = 2.f * f2sum(acc2[qi][0]) - sc0;
            Ss[(ty + 16 * qi) * 33 + tx + 16] = 2.f * f2sum(acc2[qi][1]) - sc1;
        }
        __syncthreads();

#pragma unroll
        for (int j = 0; j < 8; ++j) {
            int c = cb + rs * 8 + j;
            float v = Ss[rq * 33 + rs * 8 + j];
            if (c != qglob) {
                if (v > lv[K - 1] || (v == lv[K - 1] && c < li[K - 1])) {
                    float cvv = v; int cid = c;
#pragma unroll
                    for (int t = 0; t < K; ++t) {
                        bool better = (cvv > lv[t]) || (cvv == lv[t] && cid < li[t]);
                        float tv = lv[t]; int ti = li[t];
                        if (better) { lv[t] = cvv; li[t] = cid; cvv = tv; cid = ti; }
                    }
                }
            }
        }
    }
    __syncthreads();

#pragma unroll
    for (int j = 0; j < K; ++j) {
        Mv[(rq * 4 + rs) * K + j] = lv[j];
        Mi[(rq * 4 + rs) * K + j] = li[j];
    }
    __syncthreads();
    if (tid < 64) {
        int h[4] = {0, 0, 0, 0};
        int base = tid * 4 * K;
        float* pv = g_pkv + ((size_t)(b * N + qbase + tid) * NSPLIT + blockIdx.z) * K;
        int*   pi = g_pki + ((size_t)(b * N + qbase + tid) * NSPLIT + blockIdx.z) * K;
        for (int j = 0; j < K; ++j) {
            float bv = NEG_INF; int bi = 0x7fffffff; int bs = 0;
#pragma unroll
            for (int s = 0; s < 4; ++s) {
                if (h[s] < K) {
                    float v = Mv[base + s * K + h[s]];
                    int   i = Mi[base + s * K + h[s]];
                    if (v > bv || (v == bv && i < bi)) { bv = v; bi = i; bs = s; }
                }
            }
            h[bs]++;
            pv[j] = bv; pi[j] = bi;
        }
    }
}

// ---------------- layer-1 AC GEMM with inline w1 prep (D=3) ----------------
__global__ void __launch_bounds__(256) gemm1_kernel(const float* __restrict__ x,
                                                    const float* __restrict__ w1) {
    __shared__ float4 Xs[64];
    __shared__ float4 Ws[64];
    int tid = threadIdx.x, tx = tid & 15, ty = tid >> 4;
    int rowbase = blockIdx.x * 64, colbase = blockIdx.y * 64;

    if (tid < 64) {
        const float* p = x + (size_t)(rowbase + tid) * 3;
        Xs[tid] = make_float4(p[0], p[1], p[2], 0.f);
        int cr = colbase + tid;
        float vv[3];
#pragma unroll
        for (int e = 0; e < 3; ++e) {
            if (cr < 64) vv[e] = w1[cr * 6 + e];
            else { int o = cr - 64; vv[e] = w1[o * 6 + 3 + e] - w1[o * 6 + e]; }
        }
        Ws[tid] = make_float4(vv[0], vv[1], vv[2], 0.f);
    }
    __syncthreads();

    unsigned long long acc2[4][4];
#pragma unroll
    for (int qi = 0; qi < 4; ++qi)
#pragma unroll
        for (int ci = 0; ci < 4; ++ci) acc2[qi][ci] = 0ull;
    U64x2 xv[4], wv[4];
#pragma unroll
    for (int qi = 0; qi < 4; ++qi) xv[qi] = asu64x2(Xs[ty + 16 * qi]);
#pragma unroll
    for (int ci = 0; ci < 4; ++ci) wv[ci] = asu64x2(Ws[tx + 16 * ci]);
#pragma unroll
    for (int qi = 0; qi < 4; ++qi)
#pragma unroll
        for (int ci = 0; ci < 4; ++ci) {
            fma2(acc2[qi][ci], xv[qi].a, wv[ci].a);
            fma2(acc2[qi][ci], xv[qi].b, wv[ci].b);
        }
#pragma unroll
    for (int qi = 0; qi < 4; ++qi)
#pragma unroll
        for (int ci = 0; ci < 4; ++ci)
            g_AC[(size_t)(rowbase + ty + 16 * qi) * 128 + colbase + tx + 16 * ci] =
                f2sum(acc2[qi][ci]);
}

// ---------------- weight prep ----------------
__global__ void prep_wc_kernel(const float* __restrict__ w, int O, int D, int DPAD) {
    int i = blockIdx.x * blockDim.x + threadIdx.x;
    int total = 2 * O * DPAD;
    if (i >= total) return;
    int r = i / DPAD, d = i % DPAD;
    float v = 0.f;
    if (d < D) {
        if (r < O) v = w[r * 2 * D + d];
        else { int o = r - O; v = w[o * 2 * D + D + d] - w[o * 2 * D + d]; }
    }
    g_wc[i] = v;
}

// ---------------- register-tiled GEMM (64x64), optional w5 epilogue -----
template<int DPAD, bool W5MAX>
__global__ void __launch_bounds__(256) gemm_kernel(
    int xoff, const float* __restrict__ wext, int ldw, int ldo,
    const float* __restrict__ gg, const float* __restrict__ bb)
{
    constexpr int DC  = (DPAD < 32) ? DPAD : 32;
    constexpr int RC  = DC / 4;
    constexpr int SWM = (RC >= 8) ? 7 : 0;
    constexpr int NCH = DPAD / DC;
    constexpr int TR4 = 64 * RC;
    constexpr int NL  = (TR4 + 255) / 256;
    __shared__ float4 Xs[2 * TR4];
    __shared__ float4 Ws[2 * TR4];
    const float* x = g_cat + xoff;
    const float* w = W5MAX ? wext : g_wc;
    int tid = threadIdx.x, tx = tid & 15, ty = tid >> 4;
    int rowbase = blockIdx.x * 64, colbase = blockIdx.y * 64;
    unsigned long long acc2[4][4];
#pragma unroll
    for (int qi = 0; qi < 4; ++qi)
#pragma unroll
        for (int ci = 0; ci < 4; ++ci) acc2[qi][ci] = 0ull;

    float4 xreg[NL], wreg[NL];
    auto load_xw = [&](int ch) {
        int d0 = ch * DC;
#pragma unroll
        for (int l = 0; l < NL; ++l) {
            int i = tid + l * 256;
            if ((TR4 % 256 == 0) || i < TR4) {
                int r = i / RC, dv = i % RC;
                xreg[l] = *(const float4*)(x + (size_t)(rowbase + r) * 512 + d0 + 4 * dv);
                wreg[l] = *(const float4*)(w + (size_t)(colbase + r) * ldw + d0 + 4 * dv);
            }
        }
    };
    auto store_xw = [&](int buf) {
#pragma unroll
        for (int l = 0; l < NL; ++l) {
            int i = tid + l * 256;
            if ((TR4 % 256 == 0) || i < TR4) {
                int r = i / RC, dv = i % RC;
                Xs[buf * TR4 + r * RC + (dv ^ (r & SWM))] = xreg[l];
                Ws[buf * TR4 + r * RC + (dv ^ (r & SWM))] = wreg[l];
            }
        }
    };

    load_xw(0);
    for (int ch = 0; ch < NCH; ++ch) {
        int buf = ch & 1;
        store_xw(buf);
        if (ch + 1 < NCH) load_xw(ch + 1);
        __syncthreads();
        const float4* Xb = Xs + buf * TR4;
        const float4* Wb = Ws + buf * TR4;
#pragma unroll
        for (int dv = 0; dv < RC; ++dv) {
            U64x2 xv[4], wv[4];
#pragma unroll
            for (int qi = 0; qi < 4; ++qi)
                xv[qi] = asu64x2(Xb[(ty + 16 * qi) * RC + (dv ^ (ty & SWM))]);
#pragma unroll
            for (int ci = 0; ci < 4; ++ci)
                wv[ci] = asu64x2(Wb[(tx + 16 * ci) * RC + (dv ^ (tx & SWM))]);
#pragma unroll
            for (int qi = 0; qi < 4; ++qi)
#pragma unroll
                for (int ci = 0; ci < 4; ++ci) {
                    fma2(acc2[qi][ci], xv[qi].a, wv[ci].a);
                    fma2(acc2[qi][ci], xv[qi].b, wv[ci].b);
                }
        }
        __syncthreads();
    }

    if constexpr (!W5MAX) {
#pragma unroll
        for (int qi = 0; qi < 4; ++qi)
#pragma unroll
            for (int ci = 0; ci < 4; ++ci)
                g_AC[(size_t)(rowbase + ty + 16 * qi) * ldo + colbase + tx + 16 * ci] =
                    f2sum(acc2[qi][ci]);
    } else {
        float cm[4];
#pragma unroll
        for (int ci = 0; ci < 4; ++ci) {
            int col = colbase + tx + 16 * ci;
            float g = BNS * gg[col], be = bb[col];
            float m = NEG_INF;
#pragma unroll
            for (int qi = 0; qi < 4; ++qi) {
                float v = g * f2sum(acc2[qi][ci]) + be;
                v = (v > 0.f) ? v : SLOPE * v;
                m = fmaxf(m, v);
            }
            cm[ci] = m;
        }
        float* R = (float*)Xs;
#pragma unroll
        for (int ci = 0; ci < 4; ++ci) R[ty * 64 + tx + 16 * ci] = cm[ci];
        __syncthreads();
        if (tid < 64) {
            float m = R[tid];
#pragma unroll
            for (int t = 1; t < 16; ++t) m = fmaxf(m, R[t * 64 + tid]);
            g_part[(size_t)blockIdx.x * 1024 + colbase + tid] = m;
        }
    }
}

// ---------------- gather + bn + lrelu + max, fused next-layer sqnorm -------
__global__ void edgemax_kernel(const float* __restrict__ gamma, const float* __restrict__ beta,
                               int O, int catoff) {
    int n = blockIdx.x;
    int o = threadIdx.x;
    int b = n >> 12;
    __shared__ int sidx[K];
    __shared__ float ps[8];
    if (o < K) sidx[o] = g_knn[(size_t)n * K + o];
    __syncthreads();
    int twoO = 2 * O;
    float cterm = g_AC[(size_t)n * twoO + O + o];
    float g = BNS * gamma[o], be = beta[o];
    int base = b << 12;
    float m = NEG_INF;
#pragma unroll
    for (int j = 0; j < K; ++j) {
        float a = g_AC[(size_t)(base + sidx[j]) * twoO + o];
        float v = g * (a + cterm) + be;
        v = (v > 0.f) ? v : SLOPE * v;
        m = fmaxf(m, v);
    }
    g_cat[(size_t)n * 512 + catoff + o] = m;

    float p = m * m;
#pragma unroll
    for (int off = 16; off; off >>= 1) p += __shfl_down_sync(0xffffffffu, p, off);
    if ((o & 31) == 0) ps[o >> 5] = p;
    __syncthreads();
    if (o == 0) {
        float s = 0.f;
        int nw = O >> 5;
        for (int w = 0; w < nw; ++w) s += ps[w];
        g_sq[n] = s;
    }
}

// ---------------- final max reduce + warp-per-output MLP head -------------
__global__ void maxreduce_kernel() {
    int i = blockIdx.x * blockDim.x + threadIdx.x;
    if (i >= B * 1024) return;
    int b = i / 1024, o = i % 1024;
    float m = NEG_INF;
    for (int j = 0; j < 64; ++j)
        m = fmaxf(m, g_part[(size_t)(b * 64 + j) * 1024 + o]);
    g_h0[i] = m;
}

__global__ void fc1_kernel(const float* __restrict__ fw1, const float* __restrict__ fg1,
                           const float* __restrict__ fbt1) {
    int gw = (blockIdx.x * blockDim.x + threadIdx.x) >> 5;
    int lane = threadIdx.x & 31;
    if (gw >= B * 512) return;
    int b = gw >> 9, o = gw & 511;
    const float* h = g_h0 + b * 1024;
    const float* wr = fw1 + (size_t)o * 1024;
    float s = 0.f;
    for (int c = lane; c < 1024; c += 32) s += h[c] * wr[c];
#pragma unroll
    for (int off = 16; off; off >>= 1) s += __shfl_down_sync(0xffffffffu, s, off);
    if (lane == 0) {
        float v = BNS * fg1[o] * s + fbt1[o];
        g_y1[gw] = (v > 0.f) ? v : SLOPE * v;
    }
}

__global__ void fc2_kernel(const float* __restrict__ fw2, const float* __restrict__ fb2,
                           const float* __restrict__ fg2, const float* __restrict__ fbt2) {
    int gw = (blockIdx.x * blockDim.x + threadIdx.x) >> 5;
    int lane = threadIdx.x & 31;
    if (gw >= B * 256) return;
    int b = gw >> 8, o = gw & 255;
    const float* h = g_y1 + b * 512;
    const float* wr = fw2 + (size_t)o * 512;
    float s = 0.f;
    for (int c = lane; c < 512; c += 32) s += h[c] * wr[c];
#pragma unroll
    for (int off = 16; off; off >>= 1) s += __shfl_down_sync(0xffffffffu, s, off);
    if (lane == 0) {
        float v = BNS * fg2[o] * (s + fb2[o]) + fbt2[o];
        g_y2[gw] = (v > 0.f) ? v : SLOPE * v;
    }
}

__global__ void fc3_kernel(const float* __restrict__ fw3, const float* __restrict__ fb3,
                           float* __restrict__ out) {
    int gw = threadIdx.x >> 5;
    int lane = threadIdx.x & 31;
    if (gw >= B * 3) return;
    int b = gw / 3, o = gw % 3;
    const float* h = g_y2 + b * 256;
    const float* wr = fw3 + (size_t)o * 256;
    float s = 0.f;
    for (int c = lane; c < 256; c += 32) s += h[c] * wr[c];
#pragma unroll
    for (int off = 16; off; off >>= 1) s += __shfl_down_sync(0xffffffffu, s, off);
    if (lane == 0) out[gw] = s + fb3[o];
}

// ---------------- launch ----------------
static int knn_smem_bytes(int R4) {
    int s = 64 * R4 * 16 + 2 * 32 * R4 * 16 + 64 * 33 * 4;
    int merge = 64 * 4 * K * 8;
    return s > merge ? s : merge;
}

extern "C" void kernel_launch(void* const* d_in, const int* in_sizes, int n_in,
                              void* d_out, int out_size) {
    const float* points = (const float*)d_in[0];
    const float* w1 = (const float*)d_in[2];
    const float* g1 = (const float*)d_in[3];
    const float* b1 = (const float*)d_in[4];
    const float* w2 = (const float*)d_in[5];
    const float* g2 = (const float*)d_in[6];
    const float* b2 = (const float*)d_in[7];
    const float* w3 = (const float*)d_in[8];
    const float* g3 = (const float*)d_in[9];
    const float* b3 = (const float*)d_in[10];
    const float* w4 = (const float*)d_in[11];
    const float* g4 = (const float*)d_in[12];
    const float* b4 = (const float*)d_in[13];
    const float* w5 = (const float*)d_in[14];
    const float* g5 = (const float*)d_in[15];
    const float* b5 = (const float*)d_in[16];
    const float* fw1 = (const float*)d_in[17];
    const float* fg1 = (const float*)d_in[18];
    const float* fbt1 = (const float*)d_in[19];
    const float* fw2 = (const float*)d_in[20];
    const float* fb2 = (const float*)d_in[21];
    const float* fg2 = (const float*)d_in[22];
    const float* fbt2 = (const float*)d_in[23];
    const float* fw3 = (const float*)d_in[24];
    const float* fb3 = (const float*)d_in[25];
    float* out = (float*)d_out;

    int sm1 = 64 * 16 + 2 * 32 * 16 + 64 * 33 * 4;
    int merge1 = 64 * 4 * K * 8;
    if (merge1 > sm1) sm1 = merge1;
    int sm16 = knn_smem_bytes(16);
    int sm32 = knn_smem_bytes(32);
    static bool attr_done = false;
    if (!attr_done) {
        cudaFuncSetAttribute(knn1_kernel,     cudaFuncAttributeMaxDynamicSharedMemorySize, sm1);
        cudaFuncSetAttribute(knn_kernel<64>,  cudaFuncAttributeMaxDynamicSharedMemorySize, sm16);
        cudaFuncSetAttribute(knn_kernel<128>, cudaFuncAttributeMaxDynamicSharedMemorySize, sm32);
        attr_done = true;
    }

    dim3 knngrid(N / 64, B, NSPLIT);
    int mergegrid = (BN + 255) / 256;

    // ---- EdgeConv 1 (D=3, O=64) -> cat cols [0,64)
    knn1_kernel<<<knngrid, 256, sm1>>>(points);                       // idx 0
    knnmerge_kernel<<<mergegrid, 256>>>();                            // idx 1
    gemm1_kernel<<<dim3(BN / 64, 2), 256>>>(points, w1);              // idx 2
    edgemax_kernel<<<BN, 64>>>(g1, b1, 64, 0);                        // idx 3

    // ---- EdgeConv 2 (D=64, O=64) -> cat cols [64,128)
    knn_kernel<64><<<knngrid, 256, sm16>>>(0);                        // idx 4
    knnmerge_kernel<<<mergegrid, 256>>>();
    prep_wc_kernel<<<(2 * 64 * 64 + 255) / 256, 256>>>(w2, 64, 64, 64);
    gemm_kernel<64, false><<<dim3(BN / 64, 2), 256>>>(0, nullptr, 64, 128, nullptr, nullptr);
    edgemax_kernel<<<BN, 64>>>(g2, b2, 64, 64);

    // ---- EdgeConv 3 (D=64, O=128) -> cat cols [128,256)
    knn_kernel<64><<<knngrid, 256, sm16>>>(64);
    knnmerge_kernel<<<mergegrid, 256>>>();
    prep_wc_kernel<<<(2 * 128 * 64 + 255) / 256, 256>>>(w3, 128, 64, 64);
    gemm_kernel<64, false><<<dim3(BN / 64, 4), 256>>>(64, nullptr, 64, 256, nullptr, nullptr);
    edgemax_kernel<<<BN, 128>>>(g3, b3, 128, 128);

    // ---- EdgeConv 4 (D=128, O=256) -> cat cols [256,512)
    knn_kernel<128><<<knngrid, 256, sm32>>>(128);
    knnmerge_kernel<<<mergegrid, 256>>>();
    prep_wc_kernel<<<(2 * 256 * 128 + 255) / 256, 256>>>(w4, 256, 128, 128);
    gemm_kernel<128, false><<<dim3(BN / 64, 8), 256>>>(128, nullptr, 128, 512, nullptr, nullptr);
    edgemax_kernel<<<BN, 256>>>(g4, b4, 256, 256);

    // ---- w5 GEMM + bn + lrelu + row-block max
    gemm_kernel<512, true><<<dim3(BN / 64, 16), 256>>>(0, w5, 512, 0, g5, b5);
    maxreduce_kernel<<<(B * 1024 + 255) / 256, 256>>>();

    // ---- MLP head
    fc1_kernel<<<(B * 512 * 32 + 255) / 256, 256>>>(fw1, fg1, fbt1);
    fc2_kernel<<<(B * 256 * 32 + 255) / 256, 256>>>(fw2, fb2, fg2, fbt2);
    fc3_kernel<<<1, 384>>>(fw3, fb3, out);
}